// round 16
// baseline (speedup 1.0000x reference)
#include <cuda_runtime.h>

#define N_NODES 50000
#define N_EDGES 800000
#define N_GRAPHS 50
#define IN_FEATS 128
#define H1F 64
#define O2F 32
#define CAP 96        // max in-degree capacity (Poisson(16): P(deg>=96) ~ 0)
#define HALF 25088    // = 196 * 128, node split point for the pipeline

// ---------------- scratch (device globals; no allocation allowed) ----------
__device__ float g_z1[N_NODES * H1F];
__device__ float g_h1[N_NODES * H1F];
__device__ float g_z2[N_NODES * O2F];
__device__ float g_el[N_NODES];    // layer-1 logits
__device__ float g_er[N_NODES];
__device__ float g_el2[N_NODES];   // layer-2 logits (separate: agg1-half1 still
__device__ float g_er2[N_NODES];   // reads layer-1 logits while gemm2a runs)
__device__ int   g_cur[N_NODES];   // degree counter; zero at entry
__device__ int   g_esrc[N_NODES * CAP];   // fixed-capacity adjacency rows
__device__ float g_cnt[N_GRAPHS];

// ---------------- zero kernel (side stream, before scatter) -----------------
__global__ void zero_kernel(float* __restrict__ out) {
    for (int t = threadIdx.x; t < N_GRAPHS * O2F; t += blockDim.x)
        out[t] = 0.0f;
    if (threadIdx.x < N_GRAPHS) g_cnt[threadIdx.x] = 0.0f;
}

// ---------------- adjacency build + per-graph node-count histogram ----------
__global__ void scatter_kernel(const int* __restrict__ src,
                               const int* __restrict__ dst,
                               const int* __restrict__ gid) {
    int i = blockIdx.x * blockDim.x + threadIdx.x;
    if (i < N_NODES) atomicAdd(&g_cnt[gid[i]], 1.0f);
    if (i >= N_EDGES / 2) return;
    int j = i + N_EDGES / 2;
    int d0 = dst[i], d1 = dst[j];
    int s0 = src[i], s1 = src[j];
    int p0 = atomicAdd(&g_cur[d0], 1);
    int p1 = atomicAdd(&g_cur[d1], 1);
    if (p0 < CAP) g_esrc[d0 * CAP + p0] = s0;
    if (p1 < CAP) g_esrc[d1 * CAP + p1] = s1;
}

// ---------------- node GEMM + attention logits (NPTx4 register tiling) ------
// Covers nodes [node_base, node_base + gridDim.x*NPB), guarded by N_NODES.
template <int IN, int OUT, int NPB, int NPT>
__global__ void gemm_attn_kernel(const float* __restrict__ H,
                                 const float* __restrict__ W,
                                 const float* __restrict__ al,
                                 const float* __restrict__ ar,
                                 float* __restrict__ Z,
                                 float* __restrict__ EL,
                                 float* __restrict__ ER,
                                 int node_base) {
    constexpr int CG = OUT / 4;
    constexpr int NG = NPB / NPT;
    constexpr int NT = CG * NG;        // 256
    constexpr int KC = 32;
    constexpr int NKC = IN / KC;
    constexpr int KQ = KC / 4;
    constexpr int PITCH = NPB + 4;

    __shared__ float sx[KC * PITCH];
    __shared__ float sW[KC * OUT];

    int tid = threadIdx.x;
    int base = node_base + blockIdx.x * NPB;
    int ng = tid / CG, cg = tid % CG;
    int nn = ng * NPT;

    float4 acc[NPT];
#pragma unroll
    for (int n = 0; n < NPT; n++) acc[n] = make_float4(0.f, 0.f, 0.f, 0.f);

    for (int kc = 0; kc < NKC; kc++) {
        __syncthreads();
        for (int t = tid; t < KC * OUT / 4; t += NT)
            ((float4*)sW)[t] = ((const float4*)W)[kc * (KC * OUT / 4) + t];
        for (int t = tid; t < NPB * KQ; t += NT) {
            int node = t / KQ, kq = t % KQ;
            float4 v = make_float4(0.f, 0.f, 0.f, 0.f);
            if (base + node < N_NODES)
                v = ((const float4*)(H + (size_t)(base + node) * IN))[kc * KQ + kq];
            sx[(kq * 4 + 0) * PITCH + node] = v.x;
            sx[(kq * 4 + 1) * PITCH + node] = v.y;
            sx[(kq * 4 + 2) * PITCH + node] = v.z;
            sx[(kq * 4 + 3) * PITCH + node] = v.w;
        }
        __syncthreads();

#pragma unroll 8
        for (int k = 0; k < KC; k++) {
            float xs[NPT];
#pragma unroll
            for (int q = 0; q < NPT / 4; q++) {
                float4 xq = *(const float4*)(sx + k * PITCH + nn + q * 4);
                xs[q * 4 + 0] = xq.x;
                xs[q * 4 + 1] = xq.y;
                xs[q * 4 + 2] = xq.z;
                xs[q * 4 + 3] = xq.w;
            }
            float4 w = *(const float4*)(sW + k * OUT + cg * 4);
#pragma unroll
            for (int n = 0; n < NPT; n++) {
                acc[n].x += xs[n] * w.x;
                acc[n].y += xs[n] * w.y;
                acc[n].z += xs[n] * w.z;
                acc[n].w += xs[n] * w.w;
            }
        }
    }

    float4 av = ((const float4*)al)[cg];
    float4 rv = ((const float4*)ar)[cg];
#pragma unroll
    for (int n = 0; n < NPT; n++) {
        float l = acc[n].x * av.x + acc[n].y * av.y +
                  acc[n].z * av.z + acc[n].w * av.w;
        float r = acc[n].x * rv.x + acc[n].y * rv.y +
                  acc[n].z * rv.z + acc[n].w * rv.w;
#pragma unroll
        for (int off = CG / 2; off > 0; off >>= 1) {
            l += __shfl_xor_sync(0xffffffffu, l, off);
            r += __shfl_xor_sync(0xffffffffu, r, off);
        }
        int node = base + nn + n;
        if (node < N_NODES) {
            ((float4*)(Z + (size_t)node * OUT))[cg] = acc[n];
            if (cg == 0) { EL[node] = l; ER[node] = r; }
        }
    }
}

// ---------------- fused softmax + aggregation (max-free), warp per node -----
// Covers nodes [node_base, node_end). POOL variant scales by precomputed
// 1/cnt, pools directly, and resets g_cur[wid] for the next graph replay.
template <int OUT, bool POOL>
__global__ void node_agg_kernel(const float* __restrict__ Z,
                                const float* __restrict__ b,
                                float* __restrict__ Hout,
                                const int* __restrict__ gid,
                                float* __restrict__ out,
                                const float* __restrict__ EL,
                                const float* __restrict__ ER,
                                int node_base, int node_end) {
    constexpr int LPE = OUT / 4;
    constexpr int EPI = 32 / LPE;
    int wid  = node_base + ((blockIdx.x * blockDim.x + threadIdx.x) >> 5);
    int lane = threadIdx.x & 31;
    if (wid >= node_end) return;

    int deg = min(g_cur[wid], CAP);
    const int* row = g_esrc + (size_t)wid * CAP;
    float erd = ER[wid];
    int sub = lane / LPE;
    int fl  = lane % LPE;

    float s_lane = 0.f;
    float4 acc = make_float4(0.f, 0.f, 0.f, 0.f);

    for (int base = 0; base < deg; base += 32) {
        int t = base + lane;
        bool valid = t < deg;
        int sN = valid ? row[t] : 0;
        float a = 0.f;
        if (valid) {
            float v = EL[sN] + erd;
            v = (v > 0.f) ? v : 0.2f * v;
            a = __expf(v);
        }
        s_lane += a;

        int cnt = min(32, deg - base);
        for (int j = 0; j < cnt; j += EPI) {
            int ei = j + sub;
            float alpha = __shfl_sync(0xffffffffu, a, ei);
            int   sn    = __shfl_sync(0xffffffffu, sN, ei);
            float4 zv = ((const float4*)(Z + (size_t)sn * OUT))[fl];
            acc.x += alpha * zv.x;
            acc.y += alpha * zv.y;
            acc.z += alpha * zv.z;
            acc.w += alpha * zv.w;
        }
    }

    float s = s_lane;
#pragma unroll
    for (int off = 16; off > 0; off >>= 1)
        s += __shfl_xor_sync(0xffffffffu, s, off);
#pragma unroll
    for (int off = 16; off >= LPE; off >>= 1) {
        acc.x += __shfl_xor_sync(0xffffffffu, acc.x, off);
        acc.y += __shfl_xor_sync(0xffffffffu, acc.y, off);
        acc.z += __shfl_xor_sync(0xffffffffu, acc.z, off);
        acc.w += __shfl_xor_sync(0xffffffffu, acc.w, off);
    }

    if (POOL && lane == 0) g_cur[wid] = 0;   // restore invariant for replay

    if (lane < LPE) {
        float inv_s = (deg > 0) ? 1.f / s : 0.f;
        float4 bq = ((const float4*)b)[fl];
        float4 h;
        h.x = acc.x * inv_s + bq.x;
        h.y = acc.y * inv_s + bq.y;
        h.z = acc.z * inv_s + bq.z;
        h.w = acc.w * inv_s + bq.w;
        h.x = (h.x > 0.f) ? h.x : 0.01f * h.x;
        h.y = (h.y > 0.f) ? h.y : 0.01f * h.y;
        h.z = (h.z > 0.f) ? h.z : 0.01f * h.z;
        h.w = (h.w > 0.f) ? h.w : 0.01f * h.w;
        if (POOL) {
            int g = gid[wid];
            float inv_c = 1.0f / fmaxf(g_cnt[g], 1.0f);
            h.x *= inv_c; h.y *= inv_c; h.z *= inv_c; h.w *= inv_c;
            atomicAdd(((float4*)(out + g * O2F)) + fl, h);
        } else {
            ((float4*)(Hout + (size_t)wid * OUT))[fl] = h;
        }
    }
}

// ---------------- stream/event singletons (created once, outside capture) ---
static cudaStream_t g_s1;
static cudaEvent_t  g_evFork, g_evJoin, g_evA, g_evD;
static int g_res_init = []() {
    cudaStreamCreateWithFlags(&g_s1, cudaStreamNonBlocking);
    cudaEventCreateWithFlags(&g_evFork, cudaEventDisableTiming);
    cudaEventCreateWithFlags(&g_evJoin, cudaEventDisableTiming);
    cudaEventCreateWithFlags(&g_evA, cudaEventDisableTiming);
    cudaEventCreateWithFlags(&g_evD, cudaEventDisableTiming);
    return 0;
}();

// ---------------- host launch -------------------------------------------------
extern "C" void kernel_launch(void* const* d_in, const int* in_sizes, int n_in,
                              void* d_out, int out_size) {
    const float* x   = (const float*)d_in[0];
    const int*   src = (const int*)d_in[1];
    const int*   dst = (const int*)d_in[2];
    const int*   gid = (const int*)d_in[3];
    const float* W1  = (const float*)d_in[4];
    const float* al1 = (const float*)d_in[5];
    const float* ar1 = (const float*)d_in[6];
    const float* b1  = (const float*)d_in[7];
    const float* W2  = (const float*)d_in[8];
    const float* al2 = (const float*)d_in[9];
    const float* ar2 = (const float*)d_in[10];
    const float* b2  = (const float*)d_in[11];
    float* out = (float*)d_out;

    float *z1, *h1, *z2, *el, *er, *el2, *er2;
    cudaGetSymbolAddress((void**)&z1,  g_z1);
    cudaGetSymbolAddress((void**)&h1,  g_h1);
    cudaGetSymbolAddress((void**)&z2,  g_z2);
    cudaGetSymbolAddress((void**)&el,  g_el);
    cudaGetSymbolAddress((void**)&er,  g_er);
    cudaGetSymbolAddress((void**)&el2, g_el2);
    cudaGetSymbolAddress((void**)&er2, g_er2);

    const int TB = 256;
    const int edge2_blocks = (N_EDGES / 2 + TB - 1) / TB;
    const int agg1a_blocks = HALF * 32 / TB;                      // 3136
    const int agg1b_blocks = ((N_NODES - HALF) * 32 + TB - 1) / TB; // 3114
    const int agg2_blocks  = (N_NODES * 32) / TB;                 // 6250
    const int g2a_blocks   = HALF / 128;                          // 196
    const int g2b_blocks   = (N_NODES - HALF + 127) / 128;        // 195

    // fork: zero + adjacency/count build on side stream, gemm1 on main
    cudaEventRecord(g_evFork, 0);
    cudaStreamWaitEvent(g_s1, g_evFork, 0);

    zero_kernel<<<1, 256, 0, g_s1>>>(out);
    scatter_kernel<<<edge2_blocks, TB, 0, g_s1>>>(src, dst, gid);
    cudaEventRecord(g_evJoin, g_s1);

    gemm_attn_kernel<IN_FEATS, H1F, 128, 8>
        <<<(N_NODES + 127) / 128, 256>>>(x, W1, al1, ar1, z1, el, er, 0);

    cudaStreamWaitEvent(0, g_evJoin, 0);

    // pipelined: agg1 half0 -> (gemm2 half0 on s1) || agg1 half1 on main
    node_agg_kernel<H1F, false><<<agg1a_blocks, TB>>>(
        z1, b1, h1, gid, out, el, er, 0, HALF);
    cudaEventRecord(g_evA, 0);

    node_agg_kernel<H1F, false><<<agg1b_blocks, TB>>>(
        z1, b1, h1, gid, out, el, er, HALF, N_NODES);

    cudaStreamWaitEvent(g_s1, g_evA, 0);
    gemm_attn_kernel<H1F, O2F, 128, 4><<<g2a_blocks, 256, 0, g_s1>>>(
        h1, W2, al2, ar2, z2, el2, er2, 0);
    cudaEventRecord(g_evD, g_s1);

    gemm_attn_kernel<H1F, O2F, 128, 4><<<g2b_blocks, 256>>>(
        h1, W2, al2, ar2, z2, el2, er2, HALF);

    cudaStreamWaitEvent(0, g_evD, 0);

    node_agg_kernel<O2F, true><<<agg2_blocks, TB>>>(
        z2, b2, nullptr, gid, out, el2, er2, 0, N_NODES);
}

// round 17
// speedup vs baseline: 1.0783x; 1.0783x over previous
#include <cuda_runtime.h>

#define N_NODES 50000
#define N_EDGES 800000
#define N_GRAPHS 50
#define IN_FEATS 128
#define H1F 64
#define O2F 32
#define CAP 96     // max in-degree capacity (Poisson(16): P(deg>=96) ~ 0)

// ---------------- scratch (device globals; no allocation allowed) ----------
__device__ float g_z1[N_NODES * H1F];
__device__ float g_h1[N_NODES * H1F];
__device__ float g_z2[N_NODES * O2F];
__device__ float g_el[N_NODES];
__device__ float g_er[N_NODES];
__device__ int   g_cur[N_NODES];          // degree counter; zero at entry
__device__ int   g_esrc[N_NODES * CAP];   // fixed-capacity adjacency rows
__device__ float g_cnt[N_GRAPHS];

// ---------------- zero kernel (side stream, before scatter) -----------------
__global__ void zero_kernel(float* __restrict__ out) {
    for (int t = threadIdx.x; t < N_GRAPHS * O2F; t += blockDim.x)
        out[t] = 0.0f;
    if (threadIdx.x < N_GRAPHS) g_cnt[threadIdx.x] = 0.0f;
}

// ---------------- adjacency build + per-graph node-count histogram ----------
__global__ void scatter_kernel(const int* __restrict__ src,
                               const int* __restrict__ dst,
                               const int* __restrict__ gid) {
    int i = blockIdx.x * blockDim.x + threadIdx.x;
    if (i < N_NODES) atomicAdd(&g_cnt[gid[i]], 1.0f);
    if (i >= N_EDGES / 2) return;
    int j = i + N_EDGES / 2;
    int d0 = dst[i], d1 = dst[j];
    int s0 = src[i], s1 = src[j];
    int p0 = atomicAdd(&g_cur[d0], 1);
    int p1 = atomicAdd(&g_cur[d1], 1);
    if (p0 < CAP) g_esrc[d0 * CAP + p0] = s0;
    if (p1 < CAP) g_esrc[d1 * CAP + p1] = s1;
}

// ---------------- node GEMM + attention logits (NPTx4 register tiling) ------
template <int IN, int OUT, int NPB, int NPT>
__global__ void gemm_attn_kernel(const float* __restrict__ H,
                                 const float* __restrict__ W,
                                 const float* __restrict__ al,
                                 const float* __restrict__ ar,
                                 float* __restrict__ Z,
                                 float* __restrict__ EL,
                                 float* __restrict__ ER) {
    constexpr int CG = OUT / 4;
    constexpr int NG = NPB / NPT;
    constexpr int NT = CG * NG;        // 256
    constexpr int KC = 32;
    constexpr int NKC = IN / KC;
    constexpr int KQ = KC / 4;
    constexpr int PITCH = NPB + 4;

    __shared__ float sx[KC * PITCH];
    __shared__ float sW[KC * OUT];

    int tid = threadIdx.x;
    int base = blockIdx.x * NPB;
    int ng = tid / CG, cg = tid % CG;
    int nn = ng * NPT;

    float4 acc[NPT];
#pragma unroll
    for (int n = 0; n < NPT; n++) acc[n] = make_float4(0.f, 0.f, 0.f, 0.f);

    for (int kc = 0; kc < NKC; kc++) {
        __syncthreads();
        for (int t = tid; t < KC * OUT / 4; t += NT)
            ((float4*)sW)[t] = ((const float4*)W)[kc * (KC * OUT / 4) + t];
        for (int t = tid; t < NPB * KQ; t += NT) {
            int node = t / KQ, kq = t % KQ;
            float4 v = make_float4(0.f, 0.f, 0.f, 0.f);
            if (base + node < N_NODES)
                v = ((const float4*)(H + (size_t)(base + node) * IN))[kc * KQ + kq];
            sx[(kq * 4 + 0) * PITCH + node] = v.x;
            sx[(kq * 4 + 1) * PITCH + node] = v.y;
            sx[(kq * 4 + 2) * PITCH + node] = v.z;
            sx[(kq * 4 + 3) * PITCH + node] = v.w;
        }
        __syncthreads();

#pragma unroll 8
        for (int k = 0; k < KC; k++) {
            float xs[NPT];
#pragma unroll
            for (int q = 0; q < NPT / 4; q++) {
                float4 xq = *(const float4*)(sx + k * PITCH + nn + q * 4);
                xs[q * 4 + 0] = xq.x;
                xs[q * 4 + 1] = xq.y;
                xs[q * 4 + 2] = xq.z;
                xs[q * 4 + 3] = xq.w;
            }
            float4 w = *(const float4*)(sW + k * OUT + cg * 4);
#pragma unroll
            for (int n = 0; n < NPT; n++) {
                acc[n].x += xs[n] * w.x;
                acc[n].y += xs[n] * w.y;
                acc[n].z += xs[n] * w.z;
                acc[n].w += xs[n] * w.w;
            }
        }
    }

    float4 av = ((const float4*)al)[cg];
    float4 rv = ((const float4*)ar)[cg];
#pragma unroll
    for (int n = 0; n < NPT; n++) {
        float l = acc[n].x * av.x + acc[n].y * av.y +
                  acc[n].z * av.z + acc[n].w * av.w;
        float r = acc[n].x * rv.x + acc[n].y * rv.y +
                  acc[n].z * rv.z + acc[n].w * rv.w;
#pragma unroll
        for (int off = CG / 2; off > 0; off >>= 1) {
            l += __shfl_xor_sync(0xffffffffu, l, off);
            r += __shfl_xor_sync(0xffffffffu, r, off);
        }
        int node = base + nn + n;
        if (node < N_NODES) {
            ((float4*)(Z + (size_t)node * OUT))[cg] = acc[n];
            if (cg == 0) { EL[node] = l; ER[node] = r; }
        }
    }
}

// ---------------- fused softmax+agg: TWO independent nodes per warp ---------
// Nodes (2w, 2w+1) processed with duplicated state -> two independent
// shfl->LDG chains interleave at issue, doubling per-warp MLP. Subgroup-
// uniform alpha!=0 guards skip gathers past the shorter node's degree.
// POOL variant scales by precomputed 1/cnt and resets g_cur for replay.
template <int OUT, bool POOL>
__global__ void node_agg_kernel(const float* __restrict__ Z,
                                const float* __restrict__ b,
                                float* __restrict__ Hout,
                                const int* __restrict__ gid,
                                float* __restrict__ out) {
    constexpr int LPE = OUT / 4;
    constexpr int EPI = 32 / LPE;
    int pair = (blockIdx.x * blockDim.x + threadIdx.x) >> 5;
    int lane = threadIdx.x & 31;
    int n0 = pair * 2;
    if (n0 >= N_NODES) return;
    int n1 = n0 + 1;
    bool has1 = n1 < N_NODES;

    int deg0 = min(g_cur[n0], CAP);
    int deg1 = has1 ? min(g_cur[n1], CAP) : 0;
    const int* row0 = g_esrc + (size_t)n0 * CAP;
    const int* row1 = g_esrc + (size_t)n1 * CAP;
    float erd0 = g_er[n0];
    float erd1 = has1 ? g_er[n1] : 0.f;
    int sub = lane / LPE;
    int fl  = lane % LPE;

    float s0 = 0.f, s1 = 0.f;
    float4 acc0 = make_float4(0.f, 0.f, 0.f, 0.f);
    float4 acc1 = make_float4(0.f, 0.f, 0.f, 0.f);

    int maxdeg = max(deg0, deg1);
    for (int base = 0; base < maxdeg; base += 32) {
        int t = base + lane;
        // ---- chunk loads for both nodes (independent LDG chains) ----
        int sN0 = (t < deg0) ? row0[t] : 0;
        int sN1 = (t < deg1) ? row1[t] : 0;
        float a0 = 0.f, a1 = 0.f;
        if (t < deg0) {
            float v = g_el[sN0] + erd0;
            v = (v > 0.f) ? v : 0.2f * v;
            a0 = __expf(v);
        }
        if (t < deg1) {
            float v = g_el[sN1] + erd1;
            v = (v > 0.f) ? v : 0.2f * v;
            a1 = __expf(v);
        }
        s0 += a0;
        s1 += a1;

        int cnt = min(32, maxdeg - base);
        for (int j = 0; j < cnt; j += EPI) {
            int ei = j + sub;
            float al0 = __shfl_sync(0xffffffffu, a0, ei);
            int   sn0 = __shfl_sync(0xffffffffu, sN0, ei);
            float al1 = __shfl_sync(0xffffffffu, a1, ei);
            int   sn1 = __shfl_sync(0xffffffffu, sN1, ei);
            if (al0 != 0.f) {    // subgroup-uniform
                float4 zv = ((const float4*)(Z + (size_t)sn0 * OUT))[fl];
                acc0.x += al0 * zv.x;
                acc0.y += al0 * zv.y;
                acc0.z += al0 * zv.z;
                acc0.w += al0 * zv.w;
            }
            if (al1 != 0.f) {
                float4 zv = ((const float4*)(Z + (size_t)sn1 * OUT))[fl];
                acc1.x += al1 * zv.x;
                acc1.y += al1 * zv.y;
                acc1.z += al1 * zv.z;
                acc1.w += al1 * zv.w;
            }
        }
    }

#pragma unroll
    for (int off = 16; off > 0; off >>= 1) {
        s0 += __shfl_xor_sync(0xffffffffu, s0, off);
        s1 += __shfl_xor_sync(0xffffffffu, s1, off);
    }
#pragma unroll
    for (int off = 16; off >= LPE; off >>= 1) {
        acc0.x += __shfl_xor_sync(0xffffffffu, acc0.x, off);
        acc0.y += __shfl_xor_sync(0xffffffffu, acc0.y, off);
        acc0.z += __shfl_xor_sync(0xffffffffu, acc0.z, off);
        acc0.w += __shfl_xor_sync(0xffffffffu, acc0.w, off);
        acc1.x += __shfl_xor_sync(0xffffffffu, acc1.x, off);
        acc1.y += __shfl_xor_sync(0xffffffffu, acc1.y, off);
        acc1.z += __shfl_xor_sync(0xffffffffu, acc1.z, off);
        acc1.w += __shfl_xor_sync(0xffffffffu, acc1.w, off);
    }

    if (POOL && lane == 0) {
        g_cur[n0] = 0;                    // restore invariant for replay
        if (has1) g_cur[n1] = 0;
    }

    if (lane < LPE) {
        float4 bq = ((const float4*)b)[fl];
        // ---- node 0 epilogue ----
        {
            float inv_s = (deg0 > 0) ? 1.f / s0 : 0.f;
            float4 h;
            h.x = acc0.x * inv_s + bq.x;
            h.y = acc0.y * inv_s + bq.y;
            h.z = acc0.z * inv_s + bq.z;
            h.w = acc0.w * inv_s + bq.w;
            h.x = (h.x > 0.f) ? h.x : 0.01f * h.x;
            h.y = (h.y > 0.f) ? h.y : 0.01f * h.y;
            h.z = (h.z > 0.f) ? h.z : 0.01f * h.z;
            h.w = (h.w > 0.f) ? h.w : 0.01f * h.w;
            if (POOL) {
                int g = gid[n0];
                float inv_c = 1.0f / fmaxf(g_cnt[g], 1.0f);
                h.x *= inv_c; h.y *= inv_c; h.z *= inv_c; h.w *= inv_c;
                atomicAdd(((float4*)(out + g * O2F)) + fl, h);
            } else {
                ((float4*)(Hout + (size_t)n0 * OUT))[fl] = h;
            }
        }
        // ---- node 1 epilogue ----
        if (has1) {
            float inv_s = (deg1 > 0) ? 1.f / s1 : 0.f;
            float4 h;
            h.x = acc1.x * inv_s + bq.x;
            h.y = acc1.y * inv_s + bq.y;
            h.z = acc1.z * inv_s + bq.z;
            h.w = acc1.w * inv_s + bq.w;
            h.x = (h.x > 0.f) ? h.x : 0.01f * h.x;
            h.y = (h.y > 0.f) ? h.y : 0.01f * h.y;
            h.z = (h.z > 0.f) ? h.z : 0.01f * h.z;
            h.w = (h.w > 0.f) ? h.w : 0.01f * h.w;
            if (POOL) {
                int g = gid[n1];
                float inv_c = 1.0f / fmaxf(g_cnt[g], 1.0f);
                h.x *= inv_c; h.y *= inv_c; h.z *= inv_c; h.w *= inv_c;
                atomicAdd(((float4*)(out + g * O2F)) + fl, h);
            } else {
                ((float4*)(Hout + (size_t)n1 * OUT))[fl] = h;
            }
        }
    }
}

// ---------------- stream/event singletons (created once, outside capture) ---
static cudaStream_t g_s1;
static cudaEvent_t  g_evFork, g_evJoin;
static int g_res_init = []() {
    cudaStreamCreateWithFlags(&g_s1, cudaStreamNonBlocking);
    cudaEventCreateWithFlags(&g_evFork, cudaEventDisableTiming);
    cudaEventCreateWithFlags(&g_evJoin, cudaEventDisableTiming);
    return 0;
}();

// ---------------- host launch -------------------------------------------------
extern "C" void kernel_launch(void* const* d_in, const int* in_sizes, int n_in,
                              void* d_out, int out_size) {
    const float* x   = (const float*)d_in[0];
    const int*   src = (const int*)d_in[1];
    const int*   dst = (const int*)d_in[2];
    const int*   gid = (const int*)d_in[3];
    const float* W1  = (const float*)d_in[4];
    const float* al1 = (const float*)d_in[5];
    const float* ar1 = (const float*)d_in[6];
    const float* b1  = (const float*)d_in[7];
    const float* W2  = (const float*)d_in[8];
    const float* al2 = (const float*)d_in[9];
    const float* ar2 = (const float*)d_in[10];
    const float* b2  = (const float*)d_in[11];
    float* out = (float*)d_out;

    float *z1, *h1, *z2, *el, *er;
    cudaGetSymbolAddress((void**)&z1, g_z1);
    cudaGetSymbolAddress((void**)&h1, g_h1);
    cudaGetSymbolAddress((void**)&z2, g_z2);
    cudaGetSymbolAddress((void**)&el, g_el);
    cudaGetSymbolAddress((void**)&er, g_er);

    const int TB = 256;
    const int edge2_blocks = (N_EDGES / 2 + TB - 1) / TB;
    const int pairs        = (N_NODES + 1) / 2;                  // 25000
    const int agg_blocks   = (pairs * 32 + TB - 1) / TB;         // 3125

    // fork: zero + adjacency/count build on side stream, gemm1 on main
    cudaEventRecord(g_evFork, 0);
    cudaStreamWaitEvent(g_s1, g_evFork, 0);

    zero_kernel<<<1, 256, 0, g_s1>>>(out);
    scatter_kernel<<<edge2_blocks, TB, 0, g_s1>>>(src, dst, gid);
    cudaEventRecord(g_evJoin, g_s1);

    gemm_attn_kernel<IN_FEATS, H1F, 128, 8>
        <<<(N_NODES + 127) / 128, 256>>>(x, W1, al1, ar1, z1, el, er);

    cudaStreamWaitEvent(0, g_evJoin, 0);

    node_agg_kernel<H1F, false><<<agg_blocks, TB>>>(z1, b1, h1, gid, out);

    gemm_attn_kernel<H1F, O2F, 128, 4>
        <<<(N_NODES + 127) / 128, 256>>>(h1, W2, al2, ar2, z2, el, er);

    node_agg_kernel<O2F, true><<<agg_blocks, TB>>>(z2, b2, nullptr, gid, out);
}